// round 16
// baseline (speedup 1.0000x reference)
#include <cuda_runtime.h>
#include <cuda_fp16.h>
#include <cstdint>
#include <cstddef>

// ============================ problem dims ============================
static constexpr int BATCH = 8192;
static constexpr int INCH  = 2048;
static constexpr int NGATE = 2048;     // OUT_CH (per-gate width)

// ============================ GEMM tiling ============================
static constexpr int BM = 128;          // rows per CTA
static constexpr int BN = 32;           // output cols per gate per CTA (N_tot = 4*BN = 128)
static constexpr int NTOT = 4 * BN;     // 128 B-rows (gate-major)
static constexpr int BK = 64;           // K chunk (64 fp16 = 128 bytes/row)
static constexpr int STAGES = 3;        // 3-stage ring (depth is load-bearing; R15 lesson)
static constexpr int NCHUNK = INCH / BK;    // 32
static constexpr int HALF_CHUNKS = NCHUNK / 2;  // 16 chunks per fp16 accumulator
static constexpr int THREADS = 512;         // 16 warps: 4 (M) x 4 (N), warp tile 32x32

static constexpr int A_STAGE_BYTES = BM * 128;     // 16 KB
static constexpr int B_STAGE_BYTES = NTOT * 128;   // 16 KB
static constexpr int STAGE_BYTES = A_STAGE_BYTES + B_STAGE_BYTES;  // 32 KB
static constexpr int SM_DATA   = 1024;             // stage data offset (mbarriers below)
static constexpr int SMEM_TOTAL = SM_DATA + STAGES * STAGE_BYTES;  // 99328 -> 2 CTAs/SM

// fused convert: W-transpose blocks then input blocks
static constexpr int W_BLK_X = (4 * NGATE) / 32;   // 256
static constexpr int W_BLK_Y = INCH / 32;          // 64
static constexpr int W_BLKS  = W_BLK_X * W_BLK_Y;  // 16384
static constexpr int IN_BLKS = 2048;               // grid-stride input convert blocks
static constexpr int CVT_BLKS = W_BLKS + IN_BLKS;

// ============================ scratch (no cudaMalloc allowed) ============================
__device__ __align__(16) __half g_A [BATCH * INCH];        // 32 MB fp16 input
__device__ __align__(16) __half g_Wt[4 * NGATE * INCH];    // 32 MB fp16 W^T (K-major rows)

// ============================ PTX helpers ============================
__device__ __forceinline__ uint32_t smem_u32(const void* p) {
    uint32_t a;
    asm("{ .reg .u64 t; cvta.to.shared.u64 t, %1; cvt.u32.u64 %0, t; }" : "=r"(a) : "l"(p));
    return a;
}

#define CP_ASYNC16(dst, src) \
    asm volatile("cp.async.cg.shared.global [%0], [%1], 16;" :: "r"((uint32_t)(dst)), "l"(src) : "memory")

// one arrive on mbar when all prior cp.async of this thread complete (.noinc: count pre-included)
#define CP_ASYNC_MBAR_ARRIVE(mbar) \
    asm volatile("cp.async.mbarrier.arrive.noinc.shared::cta.b64 [%0];" :: "r"((uint32_t)(mbar)) : "memory")

#define MBARRIER_INIT(addr, cnt) \
    asm volatile("mbarrier.init.shared.b64 [%0], %1;" :: "r"((uint32_t)(addr)), "r"((uint32_t)(cnt)) : "memory")
#define MBARRIER_ARRIVE(addr) \
    asm volatile("mbarrier.arrive.release.cta.shared::cta.b64 _, [%0];" :: "r"((uint32_t)(addr)) : "memory")
#define MBARRIER_WAIT_PARITY(addr, par) do {                                            \
    uint32_t _m = (uint32_t)(addr); uint32_t _p = (uint32_t)(par); uint32_t _d;         \
    asm volatile("{ .reg .pred p; mbarrier.try_wait.parity.acquire.cta.shared::cta.b64 p, [%1], %2; selp.b32 %0,1,0,p; }" \
        : "=r"(_d) : "r"(_m), "r"(_p) : "memory");                                       \
    if (!_d) {                                                                          \
        asm volatile("{ .reg .pred P1; WL_%=: mbarrier.try_wait.parity.acquire.cta.shared::cta.b64 P1, [%0], %1, 0x989680; @P1 bra.uni WD_%=; bra.uni WL_%=; WD_%=: }" \
            :: "r"(_m), "r"(_p) : "memory");                                             \
    } } while (0)

#define LDSM_X4(r0, r1, r2, r3, addr) \
    asm volatile("ldmatrix.sync.aligned.m8n8.x4.shared.b16 {%0,%1,%2,%3}, [%4];" \
        : "=r"(r0), "=r"(r1), "=r"(r2), "=r"(r3) : "r"(addr))

// fp16-accumulate MMA: D/C are 2 regs = 4 halves
#define MMA16816F16(c, a, b0, b1) \
    asm volatile("mma.sync.aligned.m16n8k16.row.col.f16.f16.f16.f16 " \
        "{%0,%1},{%2,%3,%4,%5},{%6,%7},{%0,%1};" \
        : "+r"((c)[0]), "+r"((c)[1]) \
        : "r"((a)[0]), "r"((a)[1]), "r"((a)[2]), "r"((a)[3]), "r"(b0), "r"(b1))

// ============================ gate math ============================
__device__ __forceinline__ float sigf(float x)   { return 1.0f / (1.0f + __expf(-x)); }
__device__ __forceinline__ float tanhf_(float x) { return 1.0f - 2.0f / (1.0f + __expf(2.0f * x)); }

__device__ __forceinline__ void lstm_elem(float gf, float gi, float go, float gs,
                                          float cin, float& h, float& cout) {
    float f = sigf(gf), i = sigf(gi), o = sigf(go), s = sigf(gs);
    cout = f * cin + i * s;
    h = o * tanhf_(cout);
}

// ============================ fused convert kernel ============================
// blocks [0, W_BLKS): W [INCH][4*NGATE] fp32 -> g_Wt [4*NGATE][INCH] fp16 (transpose)
// blocks [W_BLKS, CVT_BLKS): input fp32 -> g_A fp16 (grid-stride)
__global__ void cvt_fused_kernel(const float* __restrict__ W, const float* __restrict__ in) {
    __shared__ __half tile[32][33];
    const int b = blockIdx.x;
    if (b < W_BLKS) {
        int n0 = (b % W_BLK_X) * 32;   // column of W (gate-output dim)
        int k0 = (b / W_BLK_X) * 32;   // row of W (K dim)
        int tx = threadIdx.x & 31;
        int ty = threadIdx.x >> 5;     // 0..7
        for (int r = ty; r < 32; r += 8)
            tile[r][tx] = __float2half_rn(W[(size_t)(k0 + r) * (4 * NGATE) + n0 + tx]);
        __syncthreads();
        for (int r = ty; r < 32; r += 8)
            g_Wt[(size_t)(n0 + r) * INCH + k0 + tx] = tile[tx][r];
    } else {
        const int n4 = BATCH * INCH / 4;
        int i = (b - W_BLKS) * blockDim.x + threadIdx.x;
        const int stride = IN_BLKS * blockDim.x;
        for (; i < n4; i += stride) {
            float4 v = reinterpret_cast<const float4*>(in)[i];
            __half2 a = __floats2half2_rn(v.x, v.y);
            __half2 c = __floats2half2_rn(v.z, v.w);
            uint2 u;
            u.x = *reinterpret_cast<uint32_t*>(&a);
            u.y = *reinterpret_cast<uint32_t*>(&c);
            reinterpret_cast<uint2*>(g_A)[i] = u;
        }
    }
}

// ============================ fused GEMM + LSTM epilogue ============================
__global__ __launch_bounds__(THREADS, 2) void lstm_gemm_kernel(
    const float* __restrict__ cell, const float* __restrict__ bias, float* __restrict__ out)
{
    extern __shared__ char smem[];
    const uint32_t sb = smem_u32(smem);
    const int tid = threadIdx.x, lane = tid & 31, wid = tid >> 5;
    const int wm = wid >> 2, wn = wid & 3;           // 4 x 4 warp grid, warp tile 32x32
    const int m_cta = blockIdx.y * BM;
    const int n_cta = blockIdx.x * BN;

    // mbarrier ring: full[s] at sb + s*16, empty[s] at sb + s*16 + 8
    if (tid == 0) {
        for (int s = 0; s < STAGES; s++) {
            MBARRIER_INIT(sb + s * 16,     THREADS);  // full: 512 cp.async arrivals
            MBARRIER_INIT(sb + s * 16 + 8, THREADS);  // empty: 512 consumer arrivals
        }
    }
    __syncthreads();

    // dual fp16 accumulators: [m-tile 0..1][gate 0..3][2 regs]; each covers K=1024
    uint32_t hacc0[2][4][2], hacc1[2][4][2];
#pragma unroll
    for (int mt = 0; mt < 2; mt++)
#pragma unroll
        for (int g = 0; g < 4; g++) {
            hacc0[mt][g][0] = 0u; hacc0[mt][g][1] = 0u;
            hacc1[mt][g][0] = 0u; hacc1[mt][g][1] = 0u;
        }

    // -------- producer addressing (all 512 threads, 4 cp.async each) --------
    const int c16 = tid & 7;        // 16B chunk within a 128B row
    const int r0  = tid >> 3;       // base row (0..63)
    const uint32_t swz = (uint32_t)((c16 ^ (r0 & 7)) * 16);

    // A: rows r0, r0+64  (128 rows)
    const __half* aBase = g_A + (size_t)(m_cta + r0) * INCH + c16 * 8;
    // B: smem row r = gate*32 + n_local; rows r0, r0+64
    const __half* bSrc0 = g_Wt + (size_t)((r0 >> 5) * NGATE + n_cta + (r0 & 31)) * INCH + c16 * 8;
    const __half* bSrc1 = g_Wt + (size_t)((2 + (r0 >> 5)) * NGATE + n_cta + (r0 & 31)) * INCH + c16 * 8;

    const uint32_t dA = sb + SM_DATA + (uint32_t)r0 * 128 + swz;
    const uint32_t dB = sb + SM_DATA + A_STAGE_BYTES + (uint32_t)r0 * 128 + swz;

    auto load_stage = [&](int st, int kc) {
        size_t ko = (size_t)kc * BK;
        uint32_t so = (uint32_t)st * STAGE_BYTES;
        CP_ASYNC16(dA + so,            aBase + ko);
        CP_ASYNC16(dA + so + 64 * 128, aBase + (size_t)64 * INCH + ko);
        CP_ASYNC16(dB + so,            bSrc0 + ko);
        CP_ASYNC16(dB + so + 64 * 128, bSrc1 + ko);
        CP_ASYNC_MBAR_ARRIVE(sb + (uint32_t)st * 16);   // full[st]
    };

    // pipeline cursors: producer starts phase 1 (first empty-wait passes immediately)
    int prod_stage = 0, prod_phase = 1;
    int cons_stage = 0, cons_phase = 0;

    // -------- prologue: produce chunks 0..STAGES-2 --------
#pragma unroll
    for (int p = 0; p < STAGES - 1; p++) {
        MBARRIER_WAIT_PARITY(sb + prod_stage * 16 + 8, prod_phase);   // immediate
        load_stage(prod_stage, p);
        if (++prod_stage == STAGES) { prod_stage = 0; prod_phase ^= 1; }
    }

    const int lrow  = lane & 15;        // A ldmatrix row within 16-row tile
    const int lkA   = lane >> 4;        // A ldmatrix k-half
    const int kHalf = (lane >> 3) & 1;  // B: k-half
    const int gHalf = lane >> 4;        // B: gate within pair
    const int bRowL = lane & 7;         // B row within 8

#pragma unroll
    for (int khalf = 0; khalf < 2; khalf++) {
        uint32_t (&hacc)[2][4][2] = khalf ? hacc1 : hacc0;
        for (int kci = 0; kci < HALF_CHUNKS; kci++) {
            const int kc = khalf * HALF_CHUNKS + kci;

            // produce chunk kc+STAGES-1 (backpressure via empty barrier)
            int kn = kc + STAGES - 1;
            if (kn < NCHUNK) {
                MBARRIER_WAIT_PARITY(sb + prod_stage * 16 + 8, prod_phase);
                load_stage(prod_stage, kn);
                if (++prod_stage == STAGES) { prod_stage = 0; prod_phase ^= 1; }
            }

            // consume chunk kc
            MBARRIER_WAIT_PARITY(sb + cons_stage * 16, cons_phase);
            const uint32_t sA = sb + SM_DATA + (uint32_t)cons_stage * STAGE_BYTES;
            const uint32_t sB = sA + A_STAGE_BYTES;

#pragma unroll
            for (int ks = 0; ks < 4; ks++) {
                // B fragments: 4 gates (two x4 loads, each covers 2 gates x k16)
                uint32_t b[4][2];
#pragma unroll
                for (int gp = 0; gp < 2; gp++) {
                    int g = gp * 2 + gHalf;
                    int rowB = g * 32 + wn * 8 + bRowL;
                    int ch = ks * 2 + kHalf;
                    uint32_t addr = sB + (uint32_t)rowB * 128 + (uint32_t)((ch ^ (rowB & 7)) * 16);
                    uint32_t t0, t1, t2, t3;
                    LDSM_X4(t0, t1, t2, t3, addr);
                    b[gp * 2][0] = t0; b[gp * 2][1] = t1;
                    b[gp * 2 + 1][0] = t2; b[gp * 2 + 1][1] = t3;
                }
                // A fragments: 2 m-tiles of 16x16
                uint32_t a[2][4];
#pragma unroll
                for (int mt = 0; mt < 2; mt++) {
                    int row = wm * 32 + mt * 16 + lrow;
                    int ch = ks * 2 + lkA;
                    uint32_t addr = sA + (uint32_t)row * 128 + (uint32_t)((ch ^ (row & 7)) * 16);
                    LDSM_X4(a[mt][0], a[mt][1], a[mt][2], a[mt][3], addr);
                }
#pragma unroll
                for (int mt = 0; mt < 2; mt++)
#pragma unroll
                    for (int g = 0; g < 4; g++)
                        MMA16816F16(hacc[mt][g], a[mt], b[g][0], b[g][1]);
            }

            // release the stage for reuse
            MBARRIER_ARRIVE(sb + cons_stage * 16 + 8);
            if (++cons_stage == STAGES) { cons_stage = 0; cons_phase ^= 1; }
        }
    }

    // -------- fused LSTM epilogue: combine dual fp16 accs in fp32 --------
    const int lq = lane >> 2, lr = lane & 3;
    const int cg = n_cta + wn * 8 + lr * 2;          // even column pair base

    float2 b2[4];
#pragma unroll
    for (int g = 0; g < 4; g++)
        b2[g] = *reinterpret_cast<const float2*>(bias + g * NGATE + cg);

#pragma unroll
    for (int mt = 0; mt < 2; mt++) {
        float gv[4][4];
#pragma unroll
        for (int g = 0; g < 4; g++) {
#pragma unroll
            for (int rr = 0; rr < 2; rr++) {
                __half2 lo = *reinterpret_cast<__half2*>(&hacc0[mt][g][rr]);
                __half2 hi = *reinterpret_cast<__half2*>(&hacc1[mt][g][rr]);
                float2 flo = __half22float2(lo);
                float2 fhi = __half22float2(hi);
                gv[g][rr * 2 + 0] = flo.x + fhi.x;
                gv[g][rr * 2 + 1] = flo.y + fhi.y;
            }
        }
#pragma unroll
        for (int hh = 0; hh < 2; hh++) {             // two row halves of m16
            int r = m_cta + wm * 32 + mt * 16 + lq + hh * 8;
            float2 cv = *reinterpret_cast<const float2*>(cell + (size_t)r * NGATE + cg);
            float hv[2], cn[2];
#pragma unroll
            for (int j = 0; j < 2; j++) {
                int idx = hh * 2 + j;
                float bf = j ? b2[0].y : b2[0].x;
                float bi = j ? b2[1].y : b2[1].x;
                float bo = j ? b2[2].y : b2[2].x;
                float bs = j ? b2[3].y : b2[3].x;
                float ci = j ? cv.y : cv.x;
                lstm_elem(gv[0][idx] + bf, gv[1][idx] + bi,
                          gv[2][idx] + bo, gv[3][idx] + bs,
                          ci, hv[j], cn[j]);
            }
            *reinterpret_cast<float2*>(out + (size_t)r * NGATE + cg) =
                make_float2(hv[0], hv[1]);
            *reinterpret_cast<float2*>(out + (size_t)BATCH * NGATE + (size_t)r * NGATE + cg) =
                make_float2(cn[0], cn[1]);
        }
    }
}

// ============================ launcher ============================
extern "C" void kernel_launch(void* const* d_in, const int* in_sizes, int n_in,
                              void* d_out, int out_size) {
    const float* input = (const float*)d_in[0];
    // d_in[1] = hidden (unused by the reference math)
    const float* cell  = (const float*)d_in[2];
    const float* W     = (const float*)d_in[3];
    const float* bias  = (const float*)d_in[4];
    float* out = (float*)d_out;

    cudaFuncSetAttribute(lstm_gemm_kernel,
                         cudaFuncAttributeMaxDynamicSharedMemorySize, SMEM_TOTAL);

    cvt_fused_kernel<<<CVT_BLKS, 256>>>(W, input);
    lstm_gemm_kernel<<<dim3(NGATE / BN, BATCH / BM), THREADS, SMEM_TOTAL>>>(cell, bias, out);
}

// round 17
// speedup vs baseline: 1.2103x; 1.2103x over previous
#include <cuda_runtime.h>
#include <cuda_fp16.h>
#include <cstdint>
#include <cstddef>

// ============================ problem dims ============================
static constexpr int BATCH = 8192;
static constexpr int INCH  = 2048;
static constexpr int NGATE = 2048;     // OUT_CH (per-gate width)

// ============================ GEMM tiling ============================
static constexpr int BM = 128;          // rows per CTA
static constexpr int BN = 32;           // output cols per gate per CTA (N_tot = 4*BN = 128)
static constexpr int NTOT = 4 * BN;     // 128 B-rows (gate-major)
static constexpr int BK = 64;           // K chunk (64 fp16 = 128 bytes/row)
static constexpr int STAGES = 3;
static constexpr int NCHUNK = INCH / BK;    // 32
static constexpr int HALF_CHUNKS = NCHUNK / 2;  // 16 chunks per fp16 accumulator
static constexpr int THREADS = 256;         // 8 warps: 2 (M) x 4 (N), warp tile 64x32

static constexpr int A_STAGE_BYTES = BM * 128;     // 16 KB
static constexpr int B_STAGE_BYTES = NTOT * 128;   // 16 KB
static constexpr int STAGE_BYTES = A_STAGE_BYTES + B_STAGE_BYTES;  // 32 KB
static constexpr int SM_DATA   = 1024;             // stage data offset (mbarriers below)
static constexpr int SMEM_TOTAL = SM_DATA + STAGES * STAGE_BYTES;  // 99328 -> 2 CTAs/SM

// fused convert: W-transpose blocks then input blocks
static constexpr int W_BLK_X = (4 * NGATE) / 32;   // 256
static constexpr int W_BLK_Y = INCH / 32;          // 64
static constexpr int W_BLKS  = W_BLK_X * W_BLK_Y;  // 16384
static constexpr int IN_BLKS = 2048;               // grid-stride input convert blocks
static constexpr int CVT_BLKS = W_BLKS + IN_BLKS;

// ============================ scratch (no cudaMalloc allowed) ============================
__device__ __align__(16) __half g_A [BATCH * INCH];        // 32 MB fp16 input
__device__ __align__(16) __half g_Wt[4 * NGATE * INCH];    // 32 MB fp16 W^T (K-major rows)

// ============================ PTX helpers ============================
__device__ __forceinline__ uint32_t smem_u32(const void* p) {
    uint32_t a;
    asm("{ .reg .u64 t; cvta.to.shared.u64 t, %1; cvt.u32.u64 %0, t; }" : "=r"(a) : "l"(p));
    return a;
}

#define CP_ASYNC16(dst, src) \
    asm volatile("cp.async.cg.shared.global [%0], [%1], 16;" :: "r"((uint32_t)(dst)), "l"(src) : "memory")

// one arrive on mbar when all prior cp.async of this thread complete (.noinc: count pre-included)
#define CP_ASYNC_MBAR_ARRIVE(mbar) \
    asm volatile("cp.async.mbarrier.arrive.noinc.shared::cta.b64 [%0];" :: "r"((uint32_t)(mbar)) : "memory")

#define MBARRIER_INIT(addr, cnt) \
    asm volatile("mbarrier.init.shared.b64 [%0], %1;" :: "r"((uint32_t)(addr)), "r"((uint32_t)(cnt)) : "memory")
#define MBARRIER_ARRIVE(addr) \
    asm volatile("mbarrier.arrive.release.cta.shared::cta.b64 _, [%0];" :: "r"((uint32_t)(addr)) : "memory")
#define MBARRIER_WAIT_PARITY(addr, par) do {                                            \
    uint32_t _m = (uint32_t)(addr); uint32_t _p = (uint32_t)(par); uint32_t _d;         \
    asm volatile("{ .reg .pred p; mbarrier.try_wait.parity.acquire.cta.shared::cta.b64 p, [%1], %2; selp.b32 %0,1,0,p; }" \
        : "=r"(_d) : "r"(_m), "r"(_p) : "memory");                                       \
    if (!_d) {                                                                          \
        asm volatile("{ .reg .pred P1; WL_%=: mbarrier.try_wait.parity.acquire.cta.shared::cta.b64 P1, [%0], %1, 0x989680; @P1 bra.uni WD_%=; bra.uni WL_%=; WD_%=: }" \
            :: "r"(_m), "r"(_p) : "memory");                                             \
    } } while (0)

#define LDSM_X4(r0, r1, r2, r3, addr) \
    asm volatile("ldmatrix.sync.aligned.m8n8.x4.shared.b16 {%0,%1,%2,%3}, [%4];" \
        : "=r"(r0), "=r"(r1), "=r"(r2), "=r"(r3) : "r"(addr))

// fp16-accumulate MMA: D/C are 2 regs = 4 halves
#define MMA16816F16(c, a, b0, b1) \
    asm volatile("mma.sync.aligned.m16n8k16.row.col.f16.f16.f16.f16 " \
        "{%0,%1},{%2,%3,%4,%5},{%6,%7},{%0,%1};" \
        : "+r"((c)[0]), "+r"((c)[1]) \
        : "r"((a)[0]), "r"((a)[1]), "r"((a)[2]), "r"((a)[3]), "r"(b0), "r"(b1))

// ============================ gate math ============================
__device__ __forceinline__ float sigf(float x)   { return 1.0f / (1.0f + __expf(-x)); }
__device__ __forceinline__ float tanhf_(float x) { return 1.0f - 2.0f / (1.0f + __expf(2.0f * x)); }

__device__ __forceinline__ void lstm_elem(float gf, float gi, float go, float gs,
                                          float cin, float& h, float& cout) {
    float f = sigf(gf), i = sigf(gi), o = sigf(go), s = sigf(gs);
    cout = f * cin + i * s;
    h = o * tanhf_(cout);
}

// ============================ fused convert kernel ============================
// blocks [0, W_BLKS): W [INCH][4*NGATE] fp32 -> g_Wt [4*NGATE][INCH] fp16 (transpose)
// blocks [W_BLKS, CVT_BLKS): input fp32 -> g_A fp16 (grid-stride)
__global__ void cvt_fused_kernel(const float* __restrict__ W, const float* __restrict__ in) {
    __shared__ __half tile[32][33];
    const int b = blockIdx.x;
    if (b < W_BLKS) {
        int n0 = (b % W_BLK_X) * 32;   // column of W (gate-output dim)
        int k0 = (b / W_BLK_X) * 32;   // row of W (K dim)
        int tx = threadIdx.x & 31;
        int ty = threadIdx.x >> 5;     // 0..7
        for (int r = ty; r < 32; r += 8)
            tile[r][tx] = __float2half_rn(W[(size_t)(k0 + r) * (4 * NGATE) + n0 + tx]);
        __syncthreads();
        for (int r = ty; r < 32; r += 8)
            g_Wt[(size_t)(n0 + r) * INCH + k0 + tx] = tile[tx][r];
    } else {
        const int n4 = BATCH * INCH / 4;
        int i = (b - W_BLKS) * blockDim.x + threadIdx.x;
        const int stride = IN_BLKS * blockDim.x;
        for (; i < n4; i += stride) {
            float4 v = reinterpret_cast<const float4*>(in)[i];
            __half2 a = __floats2half2_rn(v.x, v.y);
            __half2 c = __floats2half2_rn(v.z, v.w);
            uint2 u;
            u.x = *reinterpret_cast<uint32_t*>(&a);
            u.y = *reinterpret_cast<uint32_t*>(&c);
            reinterpret_cast<uint2*>(g_A)[i] = u;
        }
    }
}

// ============================ fused GEMM + LSTM epilogue ============================
__global__ __launch_bounds__(THREADS, 2) void lstm_gemm_kernel(
    const float* __restrict__ cell, const float* __restrict__ bias, float* __restrict__ out)
{
    extern __shared__ char smem[];
    const uint32_t sb = smem_u32(smem);
    const int tid = threadIdx.x, lane = tid & 31, wid = tid >> 5;
    const int wm = wid >> 2, wn = wid & 3;           // 2 x 4 warp grid
    const int m_cta = blockIdx.y * BM;
    const int n_cta = blockIdx.x * BN;

    // mbarrier ring: full[s] at sb + s*16, empty[s] at sb + s*16 + 8
    if (tid == 0) {
        for (int s = 0; s < STAGES; s++) {
            MBARRIER_INIT(sb + s * 16,     THREADS);  // full: 256 cp.async arrivals
            MBARRIER_INIT(sb + s * 16 + 8, THREADS);  // empty: 256 consumer arrivals
        }
    }
    __syncthreads();

    // dual fp16 accumulators: [m-tile][gate][2 regs = 4 halves]; each covers K=1024
    uint32_t hacc0[4][4][2], hacc1[4][4][2];
#pragma unroll
    for (int mt = 0; mt < 4; mt++)
#pragma unroll
        for (int g = 0; g < 4; g++) {
            hacc0[mt][g][0] = 0u; hacc0[mt][g][1] = 0u;
            hacc1[mt][g][0] = 0u; hacc1[mt][g][1] = 0u;
        }

    // -------- producer addressing (all 256 threads) --------
    const int c16 = tid & 7;        // 16B chunk within a 128B row
    const int r0  = tid >> 3;       // base row (0..31)
    const uint32_t swz = (uint32_t)((c16 ^ (r0 & 7)) * 16);

    const __half* aBase = g_A + (size_t)(m_cta + r0) * INCH + c16 * 8;
    const __half* bBase = g_Wt + (size_t)(n_cta + r0) * INCH + c16 * 8;

    const uint32_t dA = sb + SM_DATA + (uint32_t)r0 * 128 + swz;
    const uint32_t dB = sb + SM_DATA + A_STAGE_BYTES + (uint32_t)r0 * 128 + swz;

    auto load_stage = [&](int st, int kc) {
        size_t ko = (size_t)kc * BK;
        uint32_t so = (uint32_t)st * STAGE_BYTES;
#pragma unroll
        for (int j = 0; j < 4; j++)
            CP_ASYNC16(dA + so + (uint32_t)j * 32 * 128, aBase + (size_t)j * 32 * INCH + ko);
#pragma unroll
        for (int j = 0; j < 4; j++)
            CP_ASYNC16(dB + so + (uint32_t)j * 32 * 128,
                       bBase + (size_t)j * NGATE * INCH + ko);
        CP_ASYNC_MBAR_ARRIVE(sb + (uint32_t)st * 16);   // full[st]
    };

    // pipeline cursors: producer starts phase 1 (first empty-wait passes immediately)
    int prod_stage = 0, prod_phase = 1;
    int cons_stage = 0, cons_phase = 0;

    // -------- prologue: produce chunks 0..STAGES-2 --------
#pragma unroll
    for (int p = 0; p < STAGES - 1; p++) {
        MBARRIER_WAIT_PARITY(sb + prod_stage * 16 + 8, prod_phase);   // immediate
        load_stage(prod_stage, p);
        if (++prod_stage == STAGES) { prod_stage = 0; prod_phase ^= 1; }
    }

    const int lrow  = lane & 15;        // A ldmatrix row within 16-row tile
    const int lkA   = lane >> 4;        // A ldmatrix k-half
    const int kHalf = (lane >> 3) & 1;  // B: k-half
    const int gHalf = lane >> 4;        // B: gate within pair
    const int bRowL = lane & 7;         // B row within 8

    // per-lane LDSM row offsets (constant across chunks)
    const int aRowOff[4] = { wm * 64 + 0 * 16 + lrow, wm * 64 + 1 * 16 + lrow,
                             wm * 64 + 2 * 16 + lrow, wm * 64 + 3 * 16 + lrow };
    const int bRowOff[2] = { (0 * 2 + gHalf) * 32 + wn * 8 + bRowL,
                             (1 * 2 + gHalf) * 32 + wn * 8 + bRowL };

    // fragment double buffers
    uint32_t afrag[2][4][4];            // [buf][mt][frag]
    uint32_t bfrag[2][4][2];            // [buf][gate][frag]

    auto load_frags = [&](int buf, int ks, uint32_t sA, uint32_t sB) {
#pragma unroll
        for (int gp = 0; gp < 2; gp++) {
            int rowB = bRowOff[gp];
            int ch = ks * 2 + kHalf;
            uint32_t addr = sB + (uint32_t)rowB * 128 + (uint32_t)((ch ^ (rowB & 7)) * 16);
            uint32_t t0, t1, t2, t3;
            LDSM_X4(t0, t1, t2, t3, addr);
            bfrag[buf][gp * 2][0] = t0; bfrag[buf][gp * 2][1] = t1;
            bfrag[buf][gp * 2 + 1][0] = t2; bfrag[buf][gp * 2 + 1][1] = t3;
        }
#pragma unroll
        for (int mt = 0; mt < 4; mt++) {
            int row = aRowOff[mt];
            int ch = ks * 2 + lkA;
            uint32_t addr = sA + (uint32_t)row * 128 + (uint32_t)((ch ^ (row & 7)) * 16);
            LDSM_X4(afrag[buf][mt][0], afrag[buf][mt][1], afrag[buf][mt][2], afrag[buf][mt][3], addr);
        }
    };

#pragma unroll
    for (int khalf = 0; khalf < 2; khalf++) {
        uint32_t (&hacc)[4][4][2] = khalf ? hacc1 : hacc0;
        for (int kci = 0; kci < HALF_CHUNKS; kci++) {
            const int kc = khalf * HALF_CHUNKS + kci;

            // produce chunk kc+STAGES-1 (backpressure via empty barrier)
            int kn = kc + STAGES - 1;
            if (kn < NCHUNK) {
                MBARRIER_WAIT_PARITY(sb + prod_stage * 16 + 8, prod_phase);
                load_stage(prod_stage, kn);
                if (++prod_stage == STAGES) { prod_stage = 0; prod_phase ^= 1; }
            }

            // consume chunk kc
            MBARRIER_WAIT_PARITY(sb + cons_stage * 16, cons_phase);
            const uint32_t sA = sb + SM_DATA + (uint32_t)cons_stage * STAGE_BYTES;
            const uint32_t sB = sA + A_STAGE_BYTES;

            // software-pipelined ks loop: frags for ks+1 issue before MMAs of ks
            load_frags(0, 0, sA, sB);
#pragma unroll
            for (int ks = 0; ks < 4; ks++) {
                const int cur = ks & 1, nxt = cur ^ 1;
                if (ks < 3) load_frags(nxt, ks + 1, sA, sB);
#pragma unroll
                for (int mt = 0; mt < 4; mt++)
#pragma unroll
                    for (int g = 0; g < 4; g++)
                        MMA16816F16(hacc[mt][g], afrag[cur][mt], bfrag[cur][g][0], bfrag[cur][g][1]);
            }

            // release the stage for reuse
            MBARRIER_ARRIVE(sb + cons_stage * 16 + 8);
            if (++cons_stage == STAGES) { cons_stage = 0; cons_phase ^= 1; }
        }
    }

    // -------- fused LSTM epilogue: combine dual fp16 accs in fp32 --------
    const int lq = lane >> 2, lr = lane & 3;
    const int cg = n_cta + wn * 8 + lr * 2;          // even column pair base

    float2 b2[4];
#pragma unroll
    for (int g = 0; g < 4; g++)
        b2[g] = *reinterpret_cast<const float2*>(bias + g * NGATE + cg);

#pragma unroll
    for (int mt = 0; mt < 4; mt++) {
        float gv[4][4];
#pragma unroll
        for (int g = 0; g < 4; g++) {
#pragma unroll
            for (int rr = 0; rr < 2; rr++) {
                __half2 lo = *reinterpret_cast<__half2*>(&hacc0[mt][g][rr]);
                __half2 hi = *reinterpret_cast<__half2*>(&hacc1[mt][g][rr]);
                float2 flo = __half22float2(lo);
                float2 fhi = __half22float2(hi);
                gv[g][rr * 2 + 0] = flo.x + fhi.x;
                gv[g][rr * 2 + 1] = flo.y + fhi.y;
            }
        }
#pragma unroll
        for (int hh = 0; hh < 2; hh++) {             // two row halves of m16
            int r = m_cta + wm * 64 + mt * 16 + lq + hh * 8;
            float2 cv = *reinterpret_cast<const float2*>(cell + (size_t)r * NGATE + cg);
            float hv[2], cn[2];
#pragma unroll
            for (int j = 0; j < 2; j++) {
                int idx = hh * 2 + j;
                float bf = j ? b2[0].y : b2[0].x;
                float bi = j ? b2[1].y : b2[1].x;
                float bo = j ? b2[2].y : b2[2].x;
                float bs = j ? b2[3].y : b2[3].x;
                float ci = j ? cv.y : cv.x;
                lstm_elem(gv[0][idx] + bf, gv[1][idx] + bi,
                          gv[2][idx] + bo, gv[3][idx] + bs,
                          ci, hv[j], cn[j]);
            }
            *reinterpret_cast<float2*>(out + (size_t)r * NGATE + cg) =
                make_float2(hv[0], hv[1]);
            *reinterpret_cast<float2*>(out + (size_t)BATCH * NGATE + (size_t)r * NGATE + cg) =
                make_float2(cn[0], cn[1]);
        }
    }
}

// ============================ launcher ============================
extern "C" void kernel_launch(void* const* d_in, const int* in_sizes, int n_in,
                              void* d_out, int out_size) {
    const float* input = (const float*)d_in[0];
    // d_in[1] = hidden (unused by the reference math)
    const float* cell  = (const float*)d_in[2];
    const float* W     = (const float*)d_in[3];
    const float* bias  = (const float*)d_in[4];
    float* out = (float*)d_out;

    cudaFuncSetAttribute(lstm_gemm_kernel,
                         cudaFuncAttributeMaxDynamicSharedMemorySize, SMEM_TOTAL);

    cvt_fused_kernel<<<CVT_BLKS, 256>>>(W, input);
    lstm_gemm_kernel<<<dim3(NGATE / BN, BATCH / BM), THREADS, SMEM_TOTAL>>>(cell, bias, out);
}